// round 16
// baseline (speedup 1.0000x reference)
#include <cuda_runtime.h>

#define CH 64
#define MMAX 50000
#define CAP 80
#define OVF_MAX 8192
#define TILE 64

// Allocation-free scratch.
__device__ float4 g_S4[MMAX * (CH / 4)];   // segment sums [M][64]
__device__ float  g_deg[MMAX];
__device__ int    g_cnt[MMAX];
__device__ int2   g_bin[MMAX * CAP];       // {src, __float_as_int(ew)}
__device__ int    g_ovf_n;
__device__ int2   g_ovf[OVF_MAX];          // {dst, src}
__device__ float  g_ovf_w[OVF_MAX];

__global__ void zero_kernel(int M) {
    int i = blockIdx.x * blockDim.x + threadIdx.x;
    if (i < M) g_cnt[i] = 0;
    if (i == 0) g_ovf_n = 0;
}

// Bin each edge under its destination. Packed 8B store (src + ew bits).
__global__ void fill_kernel(const int2* __restrict__ idx2,
                            const int2* __restrict__ idx12,
                            const float2* __restrict__ ew2,
                            int E2, int E) {
    int t = blockIdx.x * blockDim.x + threadIdx.x;
    if (t >= E2) return;
    int2 ss = __ldg(&idx2[t]);
    int2 dd = __ldg(&idx12[t]);
    float2 ww = __ldg(&ew2[t]);
    int n = E - t * 2;
    #pragma unroll
    for (int j = 0; j < 2; j++) {
        if (j >= n) break;
        int src = j ? ss.y : ss.x;
        int dst = j ? dd.y : dd.x;
        float w = j ? ww.y : ww.x;
        int slot = atomicAdd(&g_cnt[dst], 1);
        if (slot < CAP) {
            g_bin[dst * CAP + slot] = make_int2(src, __float_as_int(w));
        } else {
            int o = atomicAdd(&g_ovf_n, 1);
            if (o < OVF_MAX) {
                g_ovf[o] = make_int2(dst, src);
                g_ovf_w[o] = w;
            }
        }
    }
}

// One warp per segment. No atomics, no pre-zero.
__global__ __launch_bounds__(256) void seg_kernel(const float2* __restrict__ A2,
                                                  int M) {
    int w = (blockIdx.x * blockDim.x + threadIdx.x) >> 5;
    int l = threadIdx.x & 31;
    if (w >= M) return;
    int cnt = g_cnt[w];
    if (cnt > CAP) cnt = CAP;

    float ax = 0.f, ay = 0.f, dl = 0.f;
    for (int c0 = 0; c0 < cnt; c0 += 32) {
        int nn = cnt - c0; if (nn > 32) nn = 32;
        int2 b = (l < nn) ? __ldg(&g_bin[w * CAP + c0 + l]) : make_int2(0, 0);
        if (l < nn) dl += __int_as_float(b.y);
        for (int j = 0; j < nn; j++) {
            int src = __shfl_sync(0xffffffffu, b.x, j);
            float2 v = __ldg(&A2[src * 32 + l]);
            ax += v.x; ay += v.y;
        }
    }
    #pragma unroll
    for (int o = 16; o; o >>= 1) dl += __shfl_xor_sync(0xffffffffu, dl, o);

    ((float2*)g_S4)[w * 32 + l] = make_float2(ax, ay);
    if (l == 0) g_deg[w] = dl;
}

// Apply overflow edges (normally zero of them).
__global__ void fixup_kernel(const float4* __restrict__ A4) {
    int n = g_ovf_n;
    if (n > OVF_MAX) n = OVF_MAX;
    for (int t = threadIdx.x; t < n * 16; t += blockDim.x) {
        int e = t >> 4, q = t & 15;
        int2 ds = g_ovf[e];
        float4 v = __ldg(&A4[ds.y * 16 + q]);
        float4* p = &g_S4[ds.x * 16 + q];
        asm volatile("red.global.add.v4.f32 [%0], {%1,%2,%3,%4};"
                     :: "l"(p), "f"(v.x), "f"(v.y), "f"(v.z), "f"(v.w)
                     : "memory");
        if (q == 0) atomicAdd(&g_deg[ds.x], g_ovf_w[e]);
    }
}

// ---- Tensor-core epilogue: one stacked GEMM ----
// out[m,c] = sum_k Astk[m,k]*Bstk[k,c] + deg[m]*b1[c] + b2[c]
//   Astk = [x*deg | x | S]  (64-row tile x 192)
//   Bstk = [W1^T ; W2^T ; W] (192 x 64)
// 3xTF32 split: v = hi + lo (both tf32-rounded); acc = Ah*Bh + Ah*Bl + Al*Bh.

__device__ __forceinline__ unsigned f2tf32(float x) {
    unsigned r;
    asm("cvt.rna.tf32.f32 %0, %1;" : "=r"(r) : "f"(x));
    return r;
}

#define MMA_TF32(C, a0, a1, a2, a3, b0, b1v) \
    asm volatile( \
        "mma.sync.aligned.m16n8k8.row.col.f32.tf32.tf32.f32 " \
        "{%0,%1,%2,%3}, {%4,%5,%6,%7}, {%8,%9}, {%0,%1,%2,%3};" \
        : "+f"((C)[0]), "+f"((C)[1]), "+f"((C)[2]), "+f"((C)[3]) \
        : "r"(a0), "r"(a1), "r"(a2), "r"(a3), "r"(b0), "r"(b1v))

#define APITCH 196   // A smem pitch (floats): bank = (4*row + col) % 32 -> conflict-free frags
#define BPITCH 196   // B smem pitch (n-major): bank = (4*n + k) % 32 -> conflict-free frags

__global__ __launch_bounds__(256) void final_tc(
        const float4* __restrict__ A4,
        const int* __restrict__ vn,
        const float* __restrict__ W1,
        const float* __restrict__ b1,
        const float* __restrict__ W2,
        const float* __restrict__ b2,
        const float* __restrict__ Wt,
        float* __restrict__ out,
        int M) {
    extern __shared__ float smf[];
    float*    sA   = smf;                          // [64][APITCH] fp32
    unsigned* sBh  = (unsigned*)(smf + 64 * APITCH);        // [64 n][BPITCH]
    unsigned* sBl  = (unsigned*)(smf + 64 * APITCH + 64 * BPITCH);
    float*    sDeg = smf + 64 * APITCH + 2 * 64 * BPITCH;   // [64]

    int tid = threadIdx.x;

    // --- B staging + split (once per block; weights L2-resident) ---
    for (int i = tid; i < 4096; i += 256) {        // seg 1: W1^T -> k 0..63
        float v = __ldg(&W1[i]);                   // W1[c][k], i = cc*64+kk
        int cc = i >> 6, kk = i & 63;
        unsigned h = f2tf32(v);
        unsigned l = f2tf32(v - __uint_as_float(h));
        sBh[cc * BPITCH + kk] = h;
        sBl[cc * BPITCH + kk] = l;
    }
    for (int i = tid; i < 4096; i += 256) {        // seg 2: W2^T -> k 64..127
        float v = __ldg(&W2[i]);
        int cc = i >> 6, kk = i & 63;
        unsigned h = f2tf32(v);
        unsigned l = f2tf32(v - __uint_as_float(h));
        sBh[cc * BPITCH + 64 + kk] = h;
        sBl[cc * BPITCH + 64 + kk] = l;
    }
    for (int i = tid; i < 4096; i += 256) {        // seg 3: W -> k 128..191
        float v = __ldg(&Wt[i]);                   // Wt[k][c], i = kk*64+cc
        int kk = i >> 6, cc = i & 63;
        unsigned h = f2tf32(v);
        unsigned l = f2tf32(v - __uint_as_float(h));
        sBh[cc * BPITCH + 128 + kk] = h;
        sBl[cc * BPITCH + 128 + kk] = l;
    }

    // --- A staging: 64 rows, thread = (row, quarter) ---
    int tileBase = blockIdx.x * TILE;
    {
        int r  = tid >> 2;
        int j4 = tid & 3;
        int m  = tileBase + r;
        bool ok = (m < M);
        int rowA = ok ? vn[m] : 0;
        int mc   = ok ? m : 0;
        float d  = ok ? __ldg(&g_deg[m]) : 0.f;
        if (j4 == 0) sDeg[r] = d;
        float* rowp = &sA[r * APITCH];
        #pragma unroll
        for (int jj = 0; jj < 4; jj++) {
            int q = j4 + jj * 4;
            float4 x = __ldg(&A4[rowA * 16 + q]);
            float4 s = g_S4[mc * 16 + q];
            *(float4*)&rowp[q * 4]       = make_float4(x.x * d, x.y * d, x.z * d, x.w * d);
            *(float4*)&rowp[64 + q * 4]  = x;
            *(float4*)&rowp[128 + q * 4] = s;
        }
    }
    __syncthreads();

    // --- MMA mainloop ---
    int w    = tid >> 5;
    int lane = tid & 31;
    int gid  = lane >> 2;
    int tig  = lane & 3;
    int mrow0 = (w & 3) * 16;          // 4 row-bands of 16
    int ncol0 = (w >> 2) * 32;         // 2 col-halves of 32

    float C[4][4];
    #pragma unroll
    for (int nt = 0; nt < 4; nt++)
        #pragma unroll
        for (int i = 0; i < 4; i++) C[nt][i] = 0.f;

    #pragma unroll
    for (int kc = 0; kc < 24; kc++) {
        int kb = kc * 8;
        int ar = mrow0 + gid;
        float v0 = sA[ar * APITCH + kb + tig];
        float v1 = sA[(ar + 8) * APITCH + kb + tig];
        float v2 = sA[ar * APITCH + kb + tig + 4];
        float v3 = sA[(ar + 8) * APITCH + kb + tig + 4];
        unsigned ah0 = f2tf32(v0), ah1 = f2tf32(v1), ah2 = f2tf32(v2), ah3 = f2tf32(v3);
        unsigned al0 = f2tf32(v0 - __uint_as_float(ah0));
        unsigned al1 = f2tf32(v1 - __uint_as_float(ah1));
        unsigned al2 = f2tf32(v2 - __uint_as_float(ah2));
        unsigned al3 = f2tf32(v3 - __uint_as_float(ah3));

        #pragma unroll
        for (int nt = 0; nt < 4; nt++) {
            int nn = ncol0 + nt * 8 + gid;
            unsigned bh0 = sBh[nn * BPITCH + kb + tig];
            unsigned bh1 = sBh[nn * BPITCH + kb + tig + 4];
            unsigned bl0 = sBl[nn * BPITCH + kb + tig];
            unsigned bl1 = sBl[nn * BPITCH + kb + tig + 4];
            MMA_TF32(C[nt], ah0, ah1, ah2, ah3, bh0, bh1);
            MMA_TF32(C[nt], ah0, ah1, ah2, ah3, bl0, bl1);
            MMA_TF32(C[nt], al0, al1, al2, al3, bh0, bh1);
        }
    }

    // --- Epilogue: add deg*b1 + b2, store ---
    {
        int r0 = mrow0 + gid;
        float d0 = sDeg[r0];
        float d1 = sDeg[r0 + 8];
        int m0 = tileBase + r0;
        #pragma unroll
        for (int nt = 0; nt < 4; nt++) {
            int c0 = ncol0 + nt * 8 + 2 * tig;
            float2 bb1 = __ldg((const float2*)&b1[c0]);
            float2 bb2 = __ldg((const float2*)&b2[c0]);
            if (m0 < M) {
                float2 o;
                o.x = C[nt][0] + d0 * bb1.x + bb2.x;
                o.y = C[nt][1] + d0 * bb1.y + bb2.y;
                *(float2*)&out[m0 * CH + c0] = o;
            }
            if (m0 + 8 < M) {
                float2 o;
                o.x = C[nt][2] + d1 * bb1.x + bb2.x;
                o.y = C[nt][3] + d1 * bb1.y + bb2.y;
                *(float2*)&out[(m0 + 8) * CH + c0] = o;
            }
        }
    }
}

extern "C" void kernel_launch(void* const* d_in, const int* in_sizes, int n_in,
                              void* d_out, int out_size) {
    const float* A    = (const float*)d_in[0];   // [N, 64] f32
    const int*   vn   = (const int*)d_in[1];     // [M] int32
    const int*   idx  = (const int*)d_in[2];     // [E] int32
    const int*   idx1 = (const int*)d_in[3];     // [E] int32
    const float* ew   = (const float*)d_in[4];   // [E] f32
    const float* Wt   = (const float*)d_in[5];   // [64, 64] = [CIN][COUT]
    const float* W1   = (const float*)d_in[6];   // [64, 64] = [COUT][CIN]
    const float* b1   = (const float*)d_in[7];   // [64]
    const float* W2   = (const float*)d_in[8];   // [64, 64]
    const float* b2   = (const float*)d_in[9];   // [64]
    float* out = (float*)d_out;

    int M = in_sizes[1];
    int E = in_sizes[2];

    zero_kernel<<<(M + 255) / 256, 256>>>(M);
    {
        int E2 = (E + 1) / 2;
        fill_kernel<<<(E2 + 255) / 256, 256>>>(
            (const int2*)idx, (const int2*)idx1, (const float2*)ew, E2, E);
    }
    {
        int blocks = (M * 32 + 255) / 256;
        seg_kernel<<<blocks, 256>>>((const float2*)A, M);
    }
    fixup_kernel<<<1, 256>>>((const float4*)A);
    {
        int smemBytes = (64 * APITCH + 2 * 64 * BPITCH + 64) * 4;  // ~150.6 KB
        cudaFuncSetAttribute(final_tc,
                             cudaFuncAttributeMaxDynamicSharedMemorySize,
                             smemBytes);
        int blocks = (M + TILE - 1) / TILE;
        final_tc<<<blocks, 256, smemBytes>>>(
            (const float4*)A, vn, W1, b1, W2, b2, Wt, out, M);
    }
}

// round 17
// speedup vs baseline: 1.4253x; 1.4253x over previous
#include <cuda_runtime.h>

#define CH 64
#define MMAX 50000
#define CAP 80
#define OVF_MAX 8192
#define TILE_M 32

// Allocation-free scratch.
__device__ float4 g_S4[MMAX * (CH / 4)];   // segment sums [M][64]
__device__ float  g_deg[MMAX];
__device__ int    g_cnt[MMAX];
__device__ int2   g_bin[MMAX * CAP];       // {src, __float_as_int(ew)}
__device__ int    g_ovf_n;
__device__ int2   g_ovf[OVF_MAX];          // {dst, src}
__device__ float  g_ovf_w[OVF_MAX];

#define FFMA2(acc, a, b) \
    asm("fma.rn.f32x2 %0, %1, %2, %0;" : "+l"(acc) : "l"(a), "l"(b))

__global__ void zero_kernel(int M) {
    int i = blockIdx.x * blockDim.x + threadIdx.x;
    if (i < M) g_cnt[i] = 0;
    if (i == 0) g_ovf_n = 0;
}

// Bin each edge under its destination. Packed 8B store (src + ew bits).
// Overflow (not expected at CAP=80) goes to a tiny list, applied in seg.
__global__ void fill_kernel(const int2* __restrict__ idx2,
                            const int2* __restrict__ idx12,
                            const float2* __restrict__ ew2,
                            int E2, int E) {
    int t = blockIdx.x * blockDim.x + threadIdx.x;
    if (t >= E2) return;
    int2 ss = __ldg(&idx2[t]);
    int2 dd = __ldg(&idx12[t]);
    float2 ww = __ldg(&ew2[t]);
    int n = E - t * 2;   // handle odd tail
    #pragma unroll
    for (int j = 0; j < 2; j++) {
        if (j >= n) break;
        int src = j ? ss.y : ss.x;
        int dst = j ? dd.y : dd.x;
        float w = j ? ww.y : ww.x;
        int slot = atomicAdd(&g_cnt[dst], 1);
        if (slot < CAP) {
            g_bin[dst * CAP + slot] = make_int2(src, __float_as_int(w));
        } else {
            int o = atomicAdd(&g_ovf_n, 1);
            if (o < OVF_MAX) {
                g_ovf[o] = make_int2(dst, src);
                g_ovf_w[o] = w;
            }
        }
    }
}

// One warp per segment. Bin entries loaded with ONE coalesced int2 load per
// 32-chunk; src broadcast via shfl. Plain stores — no atomics, no pre-zero.
// Overflow list (normally empty) applied inline: one uniform LDG + branch.
__global__ __launch_bounds__(256) void seg_kernel(const float2* __restrict__ A2,
                                                  int M) {
    int w = (blockIdx.x * blockDim.x + threadIdx.x) >> 5;
    int l = threadIdx.x & 31;
    if (w >= M) return;
    int cnt = g_cnt[w];
    if (cnt > CAP) cnt = CAP;

    float ax = 0.f, ay = 0.f, dl = 0.f;
    for (int c0 = 0; c0 < cnt; c0 += 32) {
        int nn = cnt - c0; if (nn > 32) nn = 32;
        int2 b = (l < nn) ? __ldg(&g_bin[w * CAP + c0 + l]) : make_int2(0, 0);
        if (l < nn) dl += __int_as_float(b.y);
        for (int j = 0; j < nn; j++) {
            int src = __shfl_sync(0xffffffffu, b.x, j);
            float2 v = __ldg(&A2[src * 32 + l]);
            ax += v.x; ay += v.y;
        }
    }

    // Overflow edges for this segment (g_ovf_n == 0 in practice).
    int novf = g_ovf_n;
    if (novf > 0) {
        if (novf > OVF_MAX) novf = OVF_MAX;
        for (int i = 0; i < novf; i++) {
            int2 ds = __ldg(&g_ovf[i]);
            if (ds.x == w) {
                float2 v = __ldg(&A2[ds.y * 32 + l]);
                ax += v.x; ay += v.y;
                if (l == 0) dl += g_ovf_w[i];
            }
        }
    }

    #pragma unroll
    for (int o = 16; o; o >>= 1) dl += __shfl_xor_sync(0xffffffffu, dl, o);

    ((float2*)g_S4)[w * 32 + l] = make_float2(ax, ay);
    if (l == 0) g_deg[w] = dl;
}

// Epilogue with packed f32x2 FMAs (proven R11 config: 32-row tiles, 444
// blocks, 3 blocks/SM, weights smem-resident).
__global__ __launch_bounds__(256, 3) void final_kernel(
        const float4* __restrict__ A4,
        const int* __restrict__ vn,
        const float* __restrict__ W1,
        const float* __restrict__ b1,
        const float* __restrict__ W2,
        const float* __restrict__ b2,
        const float* __restrict__ Wt,   // weight, layout [k][c]
        float* __restrict__ out,
        int M, int numTiles) {
    extern __shared__ float4 sm[];
    float4* sW1v = sm;                   // [16][64]: kk -> W1[c][4kk..4kk+3]
    float4* sW2v = sm + 1024;            // [16][64]
    float4* sWv  = sm + 2048;            // [16][64]: kk -> Wt[4kk..4kk+3][c]
    float4* sX   = sm + 3072;            // [32][16]
    float4* sS   = sm + 3584;            // [32][16]
    float*  sDeg = (float*)(sm + 4096);  // [32]

    int tid = threadIdx.x;
    int c = tid & 63;
    int g = tid >> 6;
    float b1c = __ldg(&b1[c]);
    float b2c = __ldg(&b2[c]);

    const float4* W1v4 = (const float4*)W1;
    const float4* W2v4 = (const float4*)W2;
    for (int i = tid; i < 1024; i += 256) {
        int kk = i >> 6, cc = i & 63;
        sW1v[i] = __ldg(&W1v4[cc * 16 + kk]);
        sW2v[i] = __ldg(&W2v4[cc * 16 + kk]);
        int k0 = kk * 4;
        sWv[i] = make_float4(__ldg(&Wt[(k0 + 0) * CH + cc]),
                             __ldg(&Wt[(k0 + 1) * CH + cc]),
                             __ldg(&Wt[(k0 + 2) * CH + cc]),
                             __ldg(&Wt[(k0 + 3) * CH + cc]));
    }

    for (int tile = blockIdx.x; tile < numTiles; tile += gridDim.x) {
        int m0 = tile * TILE_M;
        __syncthreads();
        for (int i = tid; i < TILE_M * 16; i += 256) {
            int r = i >> 4, q = i & 15;
            int m = m0 + r;
            int mc = (m < M) ? m : 0;
            int rowA = (m < M) ? vn[m] : 0;
            sX[i] = __ldg(&A4[rowA * 16 + q]);
            sS[i] = g_S4[mc * 16 + q];
        }
        if (tid < TILE_M) {
            int m = m0 + tid;
            sDeg[tid] = (m < M) ? g_deg[m] : 0.f;
        }
        __syncthreads();

        unsigned long long a1[8], a2[8], a3[8];
        #pragma unroll
        for (int r = 0; r < 8; r++) { a1[r] = 0ull; a2[r] = 0ull; a3[r] = 0ull; }

        #pragma unroll
        for (int kk = 0; kk < 16; kk++) {
            ulonglong2 w1 = *(const ulonglong2*)&sW1v[kk * 64 + c];
            ulonglong2 w2 = *(const ulonglong2*)&sW2v[kk * 64 + c];
            ulonglong2 wv = *(const ulonglong2*)&sWv [kk * 64 + c];
            #pragma unroll
            for (int r = 0; r < 8; r++) {
                ulonglong2 x = *(const ulonglong2*)&sX[(g * 8 + r) * 16 + kk];
                ulonglong2 s = *(const ulonglong2*)&sS[(g * 8 + r) * 16 + kk];
                FFMA2(a1[r], x.x, w1.x); FFMA2(a1[r], x.y, w1.y);
                FFMA2(a2[r], x.x, w2.x); FFMA2(a2[r], x.y, w2.y);
                FFMA2(a3[r], s.x, wv.x); FFMA2(a3[r], s.y, wv.y);
            }
        }

        #pragma unroll
        for (int r = 0; r < 8; r++) {
            int m = m0 + g * 8 + r;
            if (m < M) {
                unsigned lo, hi;
                float s1, s2, s3;
                asm("mov.b64 {%0,%1}, %2;" : "=r"(lo), "=r"(hi) : "l"(a1[r]));
                s1 = __uint_as_float(lo) + __uint_as_float(hi);
                asm("mov.b64 {%0,%1}, %2;" : "=r"(lo), "=r"(hi) : "l"(a2[r]));
                s2 = __uint_as_float(lo) + __uint_as_float(hi);
                asm("mov.b64 {%0,%1}, %2;" : "=r"(lo), "=r"(hi) : "l"(a3[r]));
                s3 = __uint_as_float(lo) + __uint_as_float(hi);
                float d = sDeg[g * 8 + r];
                out[m * CH + c] = d * (s1 + b1c) + s3 + s2 + b2c;
            }
        }
    }
}

extern "C" void kernel_launch(void* const* d_in, const int* in_sizes, int n_in,
                              void* d_out, int out_size) {
    const float* A    = (const float*)d_in[0];   // [N, 64] f32
    const int*   vn   = (const int*)d_in[1];     // [M] int32
    const int*   idx  = (const int*)d_in[2];     // [E] int32
    const int*   idx1 = (const int*)d_in[3];     // [E] int32
    const float* ew   = (const float*)d_in[4];   // [E] f32
    const float* Wt   = (const float*)d_in[5];   // [64, 64] = [CIN][COUT]
    const float* W1   = (const float*)d_in[6];   // [64, 64] = [COUT][CIN]
    const float* b1   = (const float*)d_in[7];   // [64]
    const float* W2   = (const float*)d_in[8];   // [64, 64]
    const float* b2   = (const float*)d_in[9];   // [64]
    float* out = (float*)d_out;

    int M = in_sizes[1];
    int E = in_sizes[2];

    zero_kernel<<<(M + 255) / 256, 256>>>(M);
    {
        int E2 = (E + 1) / 2;
        fill_kernel<<<(E2 + 255) / 256, 256>>>(
            (const int2*)idx, (const int2*)idx1, (const float2*)ew, E2, E);
    }
    {
        int blocks = (M * 32 + 255) / 256;
        seg_kernel<<<blocks, 256>>>((const float2*)A, M);
    }
    {
        int smemBytes = 4096 * sizeof(float4) + TILE_M * sizeof(float); // 65664
        cudaFuncSetAttribute(final_kernel,
                             cudaFuncAttributeMaxDynamicSharedMemorySize,
                             smemBytes);
        int numTiles = (M + TILE_M - 1) / TILE_M;
        int blocks = 444;
        if (blocks > numTiles) blocks = numTiles;
        final_kernel<<<blocks, 256, smemBytes>>>(
            (const float4*)A, vn, W1, b1, W2, b2, Wt, out, M, numTiles);
    }
}